// round 4
// baseline (speedup 1.0000x reference)
#include <cuda_runtime.h>
#include <cstdint>

#define NN 100000
#define NE 1600000
#define IN_CH 128
#define OUT_CH 64

// Scratch (device globals: no allocation allowed in kernel_launch).
__device__ int   g_deg[NN];
__device__ float g_dinv[NN];
__device__ float g_scaled[(size_t)NN * OUT_CH];   // g = (x@W)*dinv[row], 25.6 MB
__device__ float g_acc[(size_t)NN * OUT_CH];      // scatter accumulator, 25.6 MB

// ---------------------------------------------------------------------------
// 1) degree counting (self-loop added as +1 in dinv kernel)
//    edge_index is INT32 (JAX default x64-disabled downcasts int64 -> int32).
// ---------------------------------------------------------------------------
__global__ void zero_deg_kernel(int n) {
    int i = blockIdx.x * blockDim.x + threadIdx.x;
    if (i < n) g_deg[i] = 0;
}

__global__ void count_deg_kernel(const int* __restrict__ ei, int n_edges) {
    int e = blockIdx.x * blockDim.x + threadIdx.x;
    if (e < n_edges) {
        int col = ei[n_edges + e];            // edge_index[1][e] (target)
        if ((unsigned)col < NN)               // defensive: never trap
            atomicAdd(&g_deg[col], 1);
    }
}

__global__ void dinv_kernel(int n) {
    int i = blockIdx.x * blockDim.x + threadIdx.x;
    if (i < n) g_dinv[i] = rsqrtf((float)(g_deg[i] + 1));   // +1 self loop
}

// ---------------------------------------------------------------------------
// 2) h = x @ W, g = h * dinv[row]; seeds g_acc with g (self-loop term, since
//    out[c] = dinv[c]*(g[c] + sum_{row->c} g[row]) + b).
//    Tiled SGEMM: BM=64, BN=64, BK=16, 256 threads, 4x4 microtile.
// ---------------------------------------------------------------------------
__global__ __launch_bounds__(256) void gemm_scale_kernel(
    const float* __restrict__ x, const float* __restrict__ W, int n)
{
    __shared__ float As[16][64];   // As[k][m] (x tile, transposed)
    __shared__ float Bs[16][64];   // Bs[k][ncol]

    const int tid = threadIdx.x;
    const int tx  = tid & 15;      // 0..15 -> 4 output cols each
    const int ty  = tid >> 4;      // 0..15 -> 4 output rows each
    const int m0  = blockIdx.x * 64;

    const int lr = tid >> 2;              // row-in-tile 0..63 for x
    const int lk = (tid & 3) * 4;         // k offset 0,4,8,12
    const int wk = tid >> 4;              // 0..15 for W
    const int wc = (tid & 15) * 4;        // col offset

    float acc[4][4];
#pragma unroll
    for (int i = 0; i < 4; i++)
#pragma unroll
        for (int j = 0; j < 4; j++) acc[i][j] = 0.0f;

    for (int k0 = 0; k0 < IN_CH; k0 += 16) {
        float4 av = make_float4(0.f, 0.f, 0.f, 0.f);
        const int gr = m0 + lr;
        if (gr < n)
            av = *(const float4*)(x + (size_t)gr * IN_CH + k0 + lk);
        As[lk + 0][lr] = av.x;
        As[lk + 1][lr] = av.y;
        As[lk + 2][lr] = av.z;
        As[lk + 3][lr] = av.w;

        *(float4*)&Bs[wk][wc] = *(const float4*)(W + (size_t)(k0 + wk) * OUT_CH + wc);

        __syncthreads();

#pragma unroll
        for (int kk = 0; kk < 16; kk++) {
            float4 a = *(const float4*)&As[kk][ty * 4];
            float4 b = *(const float4*)&Bs[kk][tx * 4];
            acc[0][0] += a.x * b.x; acc[0][1] += a.x * b.y; acc[0][2] += a.x * b.z; acc[0][3] += a.x * b.w;
            acc[1][0] += a.y * b.x; acc[1][1] += a.y * b.y; acc[1][2] += a.y * b.z; acc[1][3] += a.y * b.w;
            acc[2][0] += a.z * b.x; acc[2][1] += a.z * b.y; acc[2][2] += a.z * b.z; acc[2][3] += a.z * b.w;
            acc[3][0] += a.w * b.x; acc[3][1] += a.w * b.y; acc[3][2] += a.w * b.z; acc[3][3] += a.w * b.w;
        }
        __syncthreads();
    }

#pragma unroll
    for (int i = 0; i < 4; i++) {
        const int r = m0 + ty * 4 + i;
        if (r < n) {
            const float di = g_dinv[r];
            float4 v;
            v.x = acc[i][0] * di;
            v.y = acc[i][1] * di;
            v.z = acc[i][2] * di;
            v.w = acc[i][3] * di;
            const size_t off = (size_t)r * OUT_CH + tx * 4;
            *(float4*)(g_scaled + off) = v;   // gather source for scatter
            *(float4*)(g_acc + off)    = v;   // accumulator seed (self loop)
        }
    }
}

// ---------------------------------------------------------------------------
// 3) edge scatter: g_acc[col] += g_scaled[row]
//    4 threads per edge; each does 4 float4 gathers + 16 scalar atomicAdds
//    (unused return -> REDG). int32 indices, bounds-guarded.
// ---------------------------------------------------------------------------
__global__ __launch_bounds__(256) void scatter_kernel(
    const int* __restrict__ ei, int n_edges)
{
    const int t = blockIdx.x * blockDim.x + threadIdx.x;
    const int e = t >> 2;
    if (e >= n_edges) return;
    const int p   = t & 3;
    const int row = ei[e];                 // source
    const int col = ei[n_edges + e];       // target
    if ((unsigned)row >= NN || (unsigned)col >= NN) return;  // defensive

    const float4* src = (const float4*)g_scaled + (size_t)row * 16;
    float*        dst = g_acc + (size_t)col * OUT_CH;

#pragma unroll
    for (int q = 0; q < 4; q++) {
        const int idx = q * 4 + p;        // 4 threads cover 4 consecutive float4s
        float4 v = src[idx];
        atomicAdd(dst + idx * 4 + 0, v.x);
        atomicAdd(dst + idx * 4 + 1, v.y);
        atomicAdd(dst + idx * 4 + 2, v.z);
        atomicAdd(dst + idx * 4 + 3, v.w);
    }
}

// ---------------------------------------------------------------------------
// 4) finalize: out = g_acc * dinv[row] + b   (plain stores to d_out only)
// ---------------------------------------------------------------------------
__global__ void finalize_kernel(float* __restrict__ out,
                                const float* __restrict__ b, int n)
{
    const int idx = blockIdx.x * blockDim.x + threadIdx.x;  // float4 index
    const int total = n * (OUT_CH / 4);
    if (idx >= total) return;
    const int row = idx >> 4;
    const int c4  = idx & 15;
    float4 v  = ((const float4*)g_acc)[idx];
    const float di = g_dinv[row];
    float4 bb = ((const float4*)b)[c4];
    v.x = v.x * di + bb.x;
    v.y = v.y * di + bb.y;
    v.z = v.z * di + bb.z;
    v.w = v.w * di + bb.w;
    ((float4*)out)[idx] = v;
}

// ---------------------------------------------------------------------------
extern "C" void kernel_launch(void* const* d_in, const int* in_sizes, int n_in,
                              void* d_out, int out_size)
{
    const float* x  = (const float*)d_in[0];
    const int*   ei = (const int*)d_in[1];     // int32 edge_index [2, E]
    const float* W  = (const float*)d_in[2];
    const float* b  = (const float*)d_in[3];
    float*       out = (float*)d_out;

    const int n = in_sizes[0] / IN_CH;   // 100000
    const int e = in_sizes[1] / 2;       // 1600000 (element count = 2*E int32)

    zero_deg_kernel<<<(n + 255) / 256, 256>>>(n);
    count_deg_kernel<<<(e + 255) / 256, 256>>>(ei, e);
    dinv_kernel<<<(n + 255) / 256, 256>>>(n);

    gemm_scale_kernel<<<(n + 63) / 64, 256>>>(x, W, n);

    const int scatter_threads = e * 4;
    scatter_kernel<<<(scatter_threads + 255) / 256, 256>>>(ei, e);

    const int fin = n * (OUT_CH / 4);
    finalize_kernel<<<(fin + 255) / 256, 256>>>(out, b, n);
}

// round 5
// speedup vs baseline: 1.7474x; 1.7474x over previous
#include <cuda_runtime.h>
#include <cstdint>

#define NN 100000
#define NE 1600000
#define IN_CH 128
#define OUT_CH 64

// Scratch (device globals: no allocation allowed in kernel_launch).
__device__ int   g_deg[NN];
__device__ float g_dinv[NN];
__device__ float g_scaled[(size_t)NN * OUT_CH];   // g = (x@W)*dinv[row], 25.6 MB
__device__ float g_acc[(size_t)NN * OUT_CH];      // scatter accumulator, 25.6 MB

// ---------------------------------------------------------------------------
// 1) degree counting (self-loop added as +1 in dinv kernel). int32 indices.
// ---------------------------------------------------------------------------
__global__ void zero_deg_kernel(int n) {
    int i = blockIdx.x * blockDim.x + threadIdx.x;
    if (i < n) g_deg[i] = 0;
}

__global__ void count_deg_kernel(const int* __restrict__ ei, int n_edges) {
    int e = blockIdx.x * blockDim.x + threadIdx.x;
    if (e < n_edges) {
        int col = ei[n_edges + e];            // edge_index[1][e] (target)
        if ((unsigned)col < NN)               // defensive: never trap
            atomicAdd(&g_deg[col], 1);
    }
}

__global__ void dinv_kernel(int n) {
    int i = blockIdx.x * blockDim.x + threadIdx.x;
    if (i < n) g_dinv[i] = rsqrtf((float)(g_deg[i] + 1));   // +1 self loop
}

// ---------------------------------------------------------------------------
// 2) h = x @ W, g = h * dinv[row]; seeds g_acc with g (self-loop term).
//    Tiled SGEMM: BM=64, BN=64, BK=16, 256 threads, 4x4 microtile.
// ---------------------------------------------------------------------------
__global__ __launch_bounds__(256) void gemm_scale_kernel(
    const float* __restrict__ x, const float* __restrict__ W, int n)
{
    __shared__ float As[16][64];   // As[k][m] (x tile, transposed)
    __shared__ float Bs[16][64];   // Bs[k][ncol]

    const int tid = threadIdx.x;
    const int tx  = tid & 15;
    const int ty  = tid >> 4;
    const int m0  = blockIdx.x * 64;

    const int lr = tid >> 2;
    const int lk = (tid & 3) * 4;
    const int wk = tid >> 4;
    const int wc = (tid & 15) * 4;

    float acc[4][4];
#pragma unroll
    for (int i = 0; i < 4; i++)
#pragma unroll
        for (int j = 0; j < 4; j++) acc[i][j] = 0.0f;

    for (int k0 = 0; k0 < IN_CH; k0 += 16) {
        float4 av = make_float4(0.f, 0.f, 0.f, 0.f);
        const int gr = m0 + lr;
        if (gr < n)
            av = *(const float4*)(x + (size_t)gr * IN_CH + k0 + lk);
        As[lk + 0][lr] = av.x;
        As[lk + 1][lr] = av.y;
        As[lk + 2][lr] = av.z;
        As[lk + 3][lr] = av.w;

        *(float4*)&Bs[wk][wc] = *(const float4*)(W + (size_t)(k0 + wk) * OUT_CH + wc);

        __syncthreads();

#pragma unroll
        for (int kk = 0; kk < 16; kk++) {
            float4 a = *(const float4*)&As[kk][ty * 4];
            float4 b = *(const float4*)&Bs[kk][tx * 4];
            acc[0][0] += a.x * b.x; acc[0][1] += a.x * b.y; acc[0][2] += a.x * b.z; acc[0][3] += a.x * b.w;
            acc[1][0] += a.y * b.x; acc[1][1] += a.y * b.y; acc[1][2] += a.y * b.z; acc[1][3] += a.y * b.w;
            acc[2][0] += a.z * b.x; acc[2][1] += a.z * b.y; acc[2][2] += a.z * b.z; acc[2][3] += a.z * b.w;
            acc[3][0] += a.w * b.x; acc[3][1] += a.w * b.y; acc[3][2] += a.w * b.z; acc[3][3] += a.w * b.w;
        }
        __syncthreads();
    }

#pragma unroll
    for (int i = 0; i < 4; i++) {
        const int r = m0 + ty * 4 + i;
        if (r < n) {
            const float di = g_dinv[r];
            float4 v;
            v.x = acc[i][0] * di;
            v.y = acc[i][1] * di;
            v.z = acc[i][2] * di;
            v.w = acc[i][3] * di;
            const size_t off = (size_t)r * OUT_CH + tx * 4;
            *(float4*)(g_scaled + off) = v;   // gather source for scatter
            *(float4*)(g_acc + off)    = v;   // accumulator seed (self loop)
        }
    }
}

// ---------------------------------------------------------------------------
// 3) edge scatter: g_acc[col] += g_scaled[row]
//    4 threads per edge; each thread handles exactly ONE float4 slice:
//    1 LDG.128 gather + 1 red.global.add.v4.f32 (sm_90+).
//    4x fewer L2 atomic ops than scalar REDG. Target is an ordinary
//    __device__ global — a legal vector-reduction target.
// ---------------------------------------------------------------------------
__device__ __forceinline__ void red_add_v4(float* p, float4 v) {
    asm volatile("red.global.add.v4.f32 [%0], {%1,%2,%3,%4};"
                 :: "l"(p), "f"(v.x), "f"(v.y), "f"(v.z), "f"(v.w)
                 : "memory");
}

__global__ __launch_bounds__(256) void scatter_kernel(
    const int* __restrict__ ei, int n_edges)
{
    const int t = blockIdx.x * blockDim.x + threadIdx.x;
    const int e = t >> 2;
    if (e >= n_edges) return;
    const int p   = t & 3;                 // which float4 of the 64B node row
    const int row = ei[e];                 // source
    const int col = ei[n_edges + e];       // target
    if ((unsigned)row >= NN || (unsigned)col >= NN) return;  // defensive

    float4 v = ((const float4*)g_scaled)[(size_t)row * 16 + p * 4 + (t & 0)];
    // p*4 would skip slices; correct slice stride is 4 float4s per row? No:
    // a node row is 16 float4s; 4 threads cover slices {p, p+4, p+8, p+12}? No.
    // Simplest correct mapping: thread p covers float4s [p*4, p*4+4) -> that's
    // 4 float4s again. Use 16 threads/edge instead? Final: p covers ONE float4
    // at index p of the FIRST quarter... Resolve by 4 float4s per thread:
#pragma unroll
    for (int q = 0; q < 4; q++) {
        float4 vv = ((const float4*)g_scaled)[(size_t)row * 16 + p + q * 4];
        red_add_v4((float*)((float4*)g_acc + (size_t)col * 16 + p + q * 4), vv);
    }
}

// ---------------------------------------------------------------------------
// 4) finalize: out = g_acc * dinv[row] + b   (plain stores to d_out only)
// ---------------------------------------------------------------------------
__global__ void finalize_kernel(float* __restrict__ out,
                                const float* __restrict__ b, int n)
{
    const int idx = blockIdx.x * blockDim.x + threadIdx.x;  // float4 index
    const int total = n * (OUT_CH / 4);
    if (idx >= total) return;
    const int row = idx >> 4;
    const int c4  = idx & 15;
    float4 v  = ((const float4*)g_acc)[idx];
    const float di = g_dinv[row];
    float4 bb = ((const float4*)b)[c4];
    v.x = v.x * di + bb.x;
    v.y = v.y * di + bb.y;
    v.z = v.z * di + bb.z;
    v.w = v.w * di + bb.w;
    ((float4*)out)[idx] = v;
}

// ---------------------------------------------------------------------------
extern "C" void kernel_launch(void* const* d_in, const int* in_sizes, int n_in,
                              void* d_out, int out_size)
{
    const float* x  = (const float*)d_in[0];
    const int*   ei = (const int*)d_in[1];     // int32 edge_index [2, E]
    const float* W  = (const float*)d_in[2];
    const float* b  = (const float*)d_in[3];
    float*       out = (float*)d_out;

    const int n = in_sizes[0] / IN_CH;   // 100000
    const int e = in_sizes[1] / 2;       // 1600000

    zero_deg_kernel<<<(n + 255) / 256, 256>>>(n);
    count_deg_kernel<<<(e + 255) / 256, 256>>>(ei, e);
    dinv_kernel<<<(n + 255) / 256, 256>>>(n);

    gemm_scale_kernel<<<(n + 63) / 64, 256>>>(x, W, n);

    scatter_kernel<<<(e * 4 + 255) / 256, 256>>>(ei, e);

    const int fin = n * (OUT_CH / 4);
    finalize_kernel<<<(fin + 255) / 256, 256>>>(out, b, n);
}

// round 6
// speedup vs baseline: 2.0068x; 1.1484x over previous
#include <cuda_runtime.h>
#include <cstdint>

#define NN 100000
#define NE 1600000
#define IN_CH 128
#define OUT_CH 64

// Scratch (device globals: no allocation allowed in kernel_launch).
__device__ int   g_deg[NN];
__device__ float g_dinv[NN];
__device__ float g_scaled[(size_t)NN * OUT_CH];   // g = (x@W)*dinv[row], 25.6 MB
__device__ float g_acc[(size_t)NN * OUT_CH];      // scatter accumulator, 25.6 MB

// ---------------------------------------------------------------------------
// 1) degree counting (self-loop added as +1 in dinv kernel). int32 indices.
// ---------------------------------------------------------------------------
__global__ void zero_deg_kernel(int n) {
    int i = blockIdx.x * blockDim.x + threadIdx.x;
    if (i < n) g_deg[i] = 0;
}

__global__ void count_deg_kernel(const int* __restrict__ ei, int n_edges) {
    int e = blockIdx.x * blockDim.x + threadIdx.x;
    if (e < n_edges) {
        int col = ei[n_edges + e];            // edge_index[1][e] (target)
        if ((unsigned)col < NN)
            atomicAdd(&g_deg[col], 1);
    }
}

__global__ void dinv_kernel(int n) {
    int i = blockIdx.x * blockDim.x + threadIdx.x;
    if (i < n) g_dinv[i] = rsqrtf((float)(g_deg[i] + 1));   // +1 self loop
}

// ---------------------------------------------------------------------------
// 2) h = x @ W via tf32 mma.sync (m16n8k8), g = h * dinv[row]; seeds g_acc.
//    BM=128, BN=64, BK=16, 256 threads = 8 warps (4 along M x 2 along N),
//    warp tile 32x32, fp32 accumulate.
// ---------------------------------------------------------------------------
__device__ __forceinline__ unsigned f2tf32(float f) {
    unsigned r;
    asm("cvt.rna.tf32.f32 %0, %1;" : "=r"(r) : "f"(f));
    return r;
}

__device__ __forceinline__ void mma_tf32(float c[4], const unsigned a[4],
                                         const unsigned b[2]) {
    asm volatile(
        "mma.sync.aligned.m16n8k8.row.col.f32.tf32.tf32.f32 "
        "{%0,%1,%2,%3}, {%4,%5,%6,%7}, {%8,%9}, {%0,%1,%2,%3};"
        : "+f"(c[0]), "+f"(c[1]), "+f"(c[2]), "+f"(c[3])
        : "r"(a[0]), "r"(a[1]), "r"(a[2]), "r"(a[3]), "r"(b[0]), "r"(b[1]));
}

#define AS_STRIDE 20   // 128 rows x 16 k, padded: conflict-free fragment LDS
#define BS_STRIDE 68   // 16 k x 64 n, padded

__global__ __launch_bounds__(256) void gemm_tc_kernel(
    const float* __restrict__ x, const float* __restrict__ W, int n)
{
    __shared__ unsigned As[128 * AS_STRIDE];  // As[m][k], tf32 bits
    __shared__ unsigned Bs[16 * BS_STRIDE];   // Bs[k][n], tf32 bits

    const int tid  = threadIdx.x;
    const int wid  = tid >> 5;
    const int lane = tid & 31;
    const int gid  = lane >> 2;     // groupID 0..7
    const int tig  = lane & 3;      // threadID_in_group 0..3
    const int wm   = wid & 3;       // warp M index 0..3
    const int wn   = wid >> 2;      // warp N index 0..1
    const int m0   = blockIdx.x * 128;

    float c[2][4][4];               // [m-sub 16][n-tile 8][frag]
#pragma unroll
    for (int s = 0; s < 2; s++)
#pragma unroll
        for (int t = 0; t < 4; t++)
#pragma unroll
            for (int f = 0; f < 4; f++) c[s][t][f] = 0.0f;

    for (int bk = 0; bk < IN_CH / 16; bk++) {
        const int k0 = bk * 16;

        // load x tile: 128x16 f32 = 512 float4, 2 per thread
#pragma unroll
        for (int i = 0; i < 2; i++) {
            const int f4 = tid + i * 256;
            const int r  = f4 >> 2;          // 0..127
            const int c4 = (f4 & 3) * 4;     // 0,4,8,12
            float4 v = make_float4(0.f, 0.f, 0.f, 0.f);
            const int gr = m0 + r;
            if (gr < n)
                v = *(const float4*)(x + (size_t)gr * IN_CH + k0 + c4);
            unsigned* dst = &As[r * AS_STRIDE + c4];
            dst[0] = f2tf32(v.x); dst[1] = f2tf32(v.y);
            dst[2] = f2tf32(v.z); dst[3] = f2tf32(v.w);
        }
        // load W tile: 16x64 f32 = 256 float4, 1 per thread
        {
            const int r  = tid >> 4;         // 0..15
            const int c4 = (tid & 15) * 4;   // 0..60
            float4 v = *(const float4*)(W + (size_t)(k0 + r) * OUT_CH + c4);
            unsigned* dst = &Bs[r * BS_STRIDE + c4];
            dst[0] = f2tf32(v.x); dst[1] = f2tf32(v.y);
            dst[2] = f2tf32(v.z); dst[3] = f2tf32(v.w);
        }
        __syncthreads();

#pragma unroll
        for (int ks = 0; ks < 2; ks++) {     // two k8 steps per BK=16
            const int kb = ks * 8;
            // A fragments (PTX m16n8k8.tf32 layout)
            unsigned a[2][4];
#pragma unroll
            for (int s = 0; s < 2; s++) {
                const int rbase = (wm * 32 + s * 16 + gid) * AS_STRIDE;
                a[s][0] = As[rbase + kb + tig];
                a[s][1] = As[rbase + 8 * AS_STRIDE + kb + tig];
                a[s][2] = As[rbase + kb + tig + 4];
                a[s][3] = As[rbase + 8 * AS_STRIDE + kb + tig + 4];
            }
            // B fragments
            unsigned b[4][2];
#pragma unroll
            for (int t = 0; t < 4; t++) {
                const int nb = wn * 32 + t * 8 + gid;
                b[t][0] = Bs[(kb + tig) * BS_STRIDE + nb];
                b[t][1] = Bs[(kb + tig + 4) * BS_STRIDE + nb];
            }
#pragma unroll
            for (int s = 0; s < 2; s++)
#pragma unroll
                for (int t = 0; t < 4; t++)
                    mma_tf32(c[s][t], a[s], b[t]);
        }
        __syncthreads();
    }

    // epilogue: scale by dinv[row], write g_scaled + seed g_acc
#pragma unroll
    for (int s = 0; s < 2; s++) {
#pragma unroll
        for (int h = 0; h < 2; h++) {        // row halves gid / gid+8
            const int row = m0 + wm * 32 + s * 16 + gid + h * 8;
            if (row < n) {
                const float di = g_dinv[row];
#pragma unroll
                for (int t = 0; t < 4; t++) {
                    const int col = wn * 32 + t * 8 + tig * 2;
                    float2 v;
                    v.x = c[s][t][h * 2 + 0] * di;
                    v.y = c[s][t][h * 2 + 1] * di;
                    const size_t off = (size_t)row * OUT_CH + col;
                    *(float2*)(g_scaled + off) = v;
                    *(float2*)(g_acc + off)    = v;
                }
            }
        }
    }
}

// ---------------------------------------------------------------------------
// 3) edge scatter: g_acc[col] += g_scaled[row]
//    4 threads per edge; each thread covers 4 float4 slices {p, p+4, p+8, p+12}
//    with 1 LDG.128 + 1 red.global.add.v4.f32 each.
// ---------------------------------------------------------------------------
__device__ __forceinline__ void red_add_v4(float* p, float4 v) {
    asm volatile("red.global.add.v4.f32 [%0], {%1,%2,%3,%4};"
                 :: "l"(p), "f"(v.x), "f"(v.y), "f"(v.z), "f"(v.w)
                 : "memory");
}

__global__ __launch_bounds__(256) void scatter_kernel(
    const int* __restrict__ ei, int n_edges)
{
    const int t = blockIdx.x * blockDim.x + threadIdx.x;
    const int e = t >> 2;
    if (e >= n_edges) return;
    const int p   = t & 3;
    const int row = ei[e];                 // source
    const int col = ei[n_edges + e];       // target
    if ((unsigned)row >= NN || (unsigned)col >= NN) return;

#pragma unroll
    for (int q = 0; q < 4; q++) {
        float4 v = ((const float4*)g_scaled)[(size_t)row * 16 + p + q * 4];
        red_add_v4((float*)((float4*)g_acc + (size_t)col * 16 + p + q * 4), v);
    }
}

// ---------------------------------------------------------------------------
// 4) finalize: out = g_acc * dinv[row] + b   (plain stores to d_out only)
// ---------------------------------------------------------------------------
__global__ void finalize_kernel(float* __restrict__ out,
                                const float* __restrict__ b, int n)
{
    const int idx = blockIdx.x * blockDim.x + threadIdx.x;  // float4 index
    const int total = n * (OUT_CH / 4);
    if (idx >= total) return;
    const int row = idx >> 4;
    const int c4  = idx & 15;
    float4 v  = ((const float4*)g_acc)[idx];
    const float di = g_dinv[row];
    float4 bb = ((const float4*)b)[c4];
    v.x = v.x * di + bb.x;
    v.y = v.y * di + bb.y;
    v.z = v.z * di + bb.z;
    v.w = v.w * di + bb.w;
    ((float4*)out)[idx] = v;
}

// ---------------------------------------------------------------------------
extern "C" void kernel_launch(void* const* d_in, const int* in_sizes, int n_in,
                              void* d_out, int out_size)
{
    const float* x  = (const float*)d_in[0];
    const int*   ei = (const int*)d_in[1];     // int32 edge_index [2, E]
    const float* W  = (const float*)d_in[2];
    const float* b  = (const float*)d_in[3];
    float*       out = (float*)d_out;

    const int n = in_sizes[0] / IN_CH;   // 100000
    const int e = in_sizes[1] / 2;       // 1600000

    zero_deg_kernel<<<(n + 255) / 256, 256>>>(n);
    count_deg_kernel<<<(e + 255) / 256, 256>>>(ei, e);
    dinv_kernel<<<(n + 255) / 256, 256>>>(n);

    gemm_tc_kernel<<<(n + 127) / 128, 256>>>(x, W, n);

    scatter_kernel<<<(e * 4 + 255) / 256, 256>>>(ei, e);

    const int fin = n * (OUT_CH / 4);
    finalize_kernel<<<(fin + 255) / 256, 256>>>(out, b, n);
}

// round 7
// speedup vs baseline: 2.5563x; 1.2738x over previous
#include <cuda_runtime.h>
#include <cstdint>

#define NN 100000
#define NE 1600000
#define IN_CH 128
#define OUT_CH 64
#define NB 391            // ceil(NN / 256)

// Scratch (device globals: no allocation allowed in kernel_launch).
__device__ int   g_deg[NN];
__device__ float g_dinv[NN];
__device__ float g_scaled[(size_t)NN * OUT_CH];   // g = (x@W)*dinv[row], 25.6 MB
__device__ int   g_blocksum[NB];
__device__ int   g_blockoff[NB];
__device__ int   g_row_start[NN + 1];
__device__ int   g_cursor[NN];
__device__ int   g_csr_src[NE];

// ---------------------------------------------------------------------------
// 1) degree counting (in-degree by target col). int32 indices.
// ---------------------------------------------------------------------------
__global__ void zero_deg_kernel(int n) {
    int i = blockIdx.x * blockDim.x + threadIdx.x;
    if (i < n) g_deg[i] = 0;
}

__global__ void count_deg_kernel(const int* __restrict__ ei, int n_edges) {
    int e = blockIdx.x * blockDim.x + threadIdx.x;
    if (e < n_edges) {
        int row = ei[e];
        int col = ei[n_edges + e];
        if ((unsigned)row < NN && (unsigned)col < NN)   // must match fill guard
            atomicAdd(&g_deg[col], 1);
    }
}

__global__ void dinv_kernel(int n) {
    int i = blockIdx.x * blockDim.x + threadIdx.x;
    if (i < n) g_dinv[i] = rsqrtf((float)(g_deg[i] + 1));   // +1 self loop
}

// ---------------------------------------------------------------------------
// 1b) exclusive scan of degrees -> row_start (3-kernel block scan)
// ---------------------------------------------------------------------------
__global__ void block_sum_kernel(int n) {
    __shared__ int s[256];
    int i = blockIdx.x * 256 + threadIdx.x;
    s[threadIdx.x] = (i < n) ? g_deg[i] : 0;
    __syncthreads();
    for (int st = 128; st > 0; st >>= 1) {
        if (threadIdx.x < st) s[threadIdx.x] += s[threadIdx.x + st];
        __syncthreads();
    }
    if (threadIdx.x == 0) g_blocksum[blockIdx.x] = s[0];
}

__global__ void scan_blocksums_kernel(int nb) {   // single block, 512 threads
    __shared__ int s[512];
    int t = threadIdx.x;
    int v0 = (t < nb) ? g_blocksum[t] : 0;
    s[t] = v0;
    __syncthreads();
    for (int off = 1; off < 512; off <<= 1) {
        int v = (t >= off) ? s[t - off] : 0;
        __syncthreads();
        s[t] += v;
        __syncthreads();
    }
    if (t < nb) g_blockoff[t] = s[t] - v0;        // exclusive
}

__global__ void scan_final_kernel(int n) {
    __shared__ int s[256];
    int i = blockIdx.x * 256 + threadIdx.x;
    int v = (i < n) ? g_deg[i] : 0;
    s[threadIdx.x] = v;
    __syncthreads();
    for (int off = 1; off < 256; off <<= 1) {
        int u = (threadIdx.x >= off) ? s[threadIdx.x - off] : 0;
        __syncthreads();
        s[threadIdx.x] += u;
        __syncthreads();
    }
    int excl = s[threadIdx.x] - v + g_blockoff[blockIdx.x];
    if (i < n) {
        g_row_start[i] = excl;
        g_cursor[i]    = excl;
        if (i == n - 1) g_row_start[n] = excl + v;
    }
}

// ---------------------------------------------------------------------------
// 1c) fill CSR: for each edge, place src at cursor[col]++
// ---------------------------------------------------------------------------
__global__ void fill_csr_kernel(const int* __restrict__ ei, int n_edges) {
    int e = blockIdx.x * blockDim.x + threadIdx.x;
    if (e < n_edges) {
        int row = ei[e];
        int col = ei[n_edges + e];
        if ((unsigned)row < NN && (unsigned)col < NN) {
            int pos = atomicAdd(&g_cursor[col], 1);
            g_csr_src[pos] = row;
        }
    }
}

// ---------------------------------------------------------------------------
// 2) h = x @ W via tf32 mma.sync (m16n8k8), g = h * dinv[row] -> g_scaled.
// ---------------------------------------------------------------------------
__device__ __forceinline__ unsigned f2tf32(float f) {
    unsigned r;
    asm("cvt.rna.tf32.f32 %0, %1;" : "=r"(r) : "f"(f));
    return r;
}

__device__ __forceinline__ void mma_tf32(float c[4], const unsigned a[4],
                                         const unsigned b[2]) {
    asm volatile(
        "mma.sync.aligned.m16n8k8.row.col.f32.tf32.tf32.f32 "
        "{%0,%1,%2,%3}, {%4,%5,%6,%7}, {%8,%9}, {%0,%1,%2,%3};"
        : "+f"(c[0]), "+f"(c[1]), "+f"(c[2]), "+f"(c[3])
        : "r"(a[0]), "r"(a[1]), "r"(a[2]), "r"(a[3]), "r"(b[0]), "r"(b[1]));
}

#define AS_STRIDE 20
#define BS_STRIDE 68

__global__ __launch_bounds__(256) void gemm_tc_kernel(
    const float* __restrict__ x, const float* __restrict__ W, int n)
{
    __shared__ unsigned As[128 * AS_STRIDE];
    __shared__ unsigned Bs[16 * BS_STRIDE];

    const int tid  = threadIdx.x;
    const int wid  = tid >> 5;
    const int lane = tid & 31;
    const int gid  = lane >> 2;
    const int tig  = lane & 3;
    const int wm   = wid & 3;
    const int wn   = wid >> 2;
    const int m0   = blockIdx.x * 128;

    float c[2][4][4];
#pragma unroll
    for (int s = 0; s < 2; s++)
#pragma unroll
        for (int t = 0; t < 4; t++)
#pragma unroll
            for (int f = 0; f < 4; f++) c[s][t][f] = 0.0f;

    for (int bk = 0; bk < IN_CH / 16; bk++) {
        const int k0 = bk * 16;
#pragma unroll
        for (int i = 0; i < 2; i++) {
            const int f4 = tid + i * 256;
            const int r  = f4 >> 2;
            const int c4 = (f4 & 3) * 4;
            float4 v = make_float4(0.f, 0.f, 0.f, 0.f);
            const int gr = m0 + r;
            if (gr < n)
                v = *(const float4*)(x + (size_t)gr * IN_CH + k0 + c4);
            unsigned* dst = &As[r * AS_STRIDE + c4];
            dst[0] = f2tf32(v.x); dst[1] = f2tf32(v.y);
            dst[2] = f2tf32(v.z); dst[3] = f2tf32(v.w);
        }
        {
            const int r  = tid >> 4;
            const int c4 = (tid & 15) * 4;
            float4 v = *(const float4*)(W + (size_t)(k0 + r) * OUT_CH + c4);
            unsigned* dst = &Bs[r * BS_STRIDE + c4];
            dst[0] = f2tf32(v.x); dst[1] = f2tf32(v.y);
            dst[2] = f2tf32(v.z); dst[3] = f2tf32(v.w);
        }
        __syncthreads();

#pragma unroll
        for (int ks = 0; ks < 2; ks++) {
            const int kb = ks * 8;
            unsigned a[2][4];
#pragma unroll
            for (int s = 0; s < 2; s++) {
                const int rbase = (wm * 32 + s * 16 + gid) * AS_STRIDE;
                a[s][0] = As[rbase + kb + tig];
                a[s][1] = As[rbase + 8 * AS_STRIDE + kb + tig];
                a[s][2] = As[rbase + kb + tig + 4];
                a[s][3] = As[rbase + 8 * AS_STRIDE + kb + tig + 4];
            }
            unsigned b[4][2];
#pragma unroll
            for (int t = 0; t < 4; t++) {
                const int nb = wn * 32 + t * 8 + gid;
                b[t][0] = Bs[(kb + tig) * BS_STRIDE + nb];
                b[t][1] = Bs[(kb + tig + 4) * BS_STRIDE + nb];
            }
#pragma unroll
            for (int s = 0; s < 2; s++)
#pragma unroll
                for (int t = 0; t < 4; t++)
                    mma_tf32(c[s][t], a[s], b[t]);
        }
        __syncthreads();
    }

    // epilogue: scale by dinv[row], write g_scaled only
#pragma unroll
    for (int s = 0; s < 2; s++) {
#pragma unroll
        for (int h = 0; h < 2; h++) {
            const int row = m0 + wm * 32 + s * 16 + gid + h * 8;
            if (row < n) {
                const float di = g_dinv[row];
#pragma unroll
                for (int t = 0; t < 4; t++) {
                    const int col = wn * 32 + t * 8 + tig * 2;
                    float2 v;
                    v.x = c[s][t][h * 2 + 0] * di;
                    v.y = c[s][t][h * 2 + 1] * di;
                    *(float2*)(g_scaled + (size_t)row * OUT_CH + col) = v;
                }
            }
        }
    }
}

// ---------------------------------------------------------------------------
// 3) pull: one warp per node. acc = g[c] + sum_{src in N(c)} g[src];
//    out[c] = acc * dinv[c] + b.  No atomics, writes d_out once. Each lane
//    owns a float2 (64 cols / 32 lanes). Edge ids batch-loaded coalesced,
//    broadcast via shfl.
// ---------------------------------------------------------------------------
__global__ __launch_bounds__(256) void pull_kernel(
    float* __restrict__ out, const float* __restrict__ bias, int n)
{
    const int warp = (blockIdx.x * 256 + threadIdx.x) >> 5;
    const int lane = threadIdx.x & 31;
    if (warp >= n) return;

    const int start = g_row_start[warp];
    const int end   = g_row_start[warp + 1];

    const float2* base = (const float2*)g_scaled;
    float2 acc = base[(size_t)warp * 32 + lane];        // self loop g[c]

    for (int j = start; j < end; j += 32) {
        const int id  = (j + lane < end) ? g_csr_src[j + lane] : 0;
        const int cnt = min(32, end - j);
        for (int k = 0; k < cnt; k++) {
            const int src = __shfl_sync(0xffffffff, id, k);
            if ((unsigned)src < NN) {
                float2 v = base[(size_t)src * 32 + lane];
                acc.x += v.x;
                acc.y += v.y;
            }
        }
    }

    const float di = g_dinv[warp];
    float2 bb = ((const float2*)bias)[lane];
    float2 o;
    o.x = acc.x * di + bb.x;
    o.y = acc.y * di + bb.y;
    ((float2*)out)[(size_t)warp * 32 + lane] = o;
}

// ---------------------------------------------------------------------------
extern "C" void kernel_launch(void* const* d_in, const int* in_sizes, int n_in,
                              void* d_out, int out_size)
{
    const float* x  = (const float*)d_in[0];
    const int*   ei = (const int*)d_in[1];     // int32 edge_index [2, E]
    const float* W  = (const float*)d_in[2];
    const float* b  = (const float*)d_in[3];
    float*       out = (float*)d_out;

    const int n = in_sizes[0] / IN_CH;   // 100000
    const int e = in_sizes[1] / 2;       // 1600000

    zero_deg_kernel<<<(n + 255) / 256, 256>>>(n);
    count_deg_kernel<<<(e + 255) / 256, 256>>>(ei, e);
    dinv_kernel<<<(n + 255) / 256, 256>>>(n);

    const int nb = (n + 255) / 256;
    block_sum_kernel<<<nb, 256>>>(n);
    scan_blocksums_kernel<<<1, 512>>>(nb);
    scan_final_kernel<<<nb, 256>>>(n);

    gemm_tc_kernel<<<(n + 127) / 128, 256>>>(x, W, n);

    fill_csr_kernel<<<(e + 255) / 256, 256>>>(ei, e);

    pull_kernel<<<(n * 32 + 255) / 256, 256>>>(out, b, n);
}

// round 8
// speedup vs baseline: 2.6035x; 1.0185x over previous
#include <cuda_runtime.h>
#include <cuda_fp16.h>
#include <cstdint>

#define NN 100000
#define NE 1600000
#define IN_CH 128
#define OUT_CH 64
#define NB 391            // ceil(NN / 256)

// Scratch (device globals: no allocation allowed in kernel_launch).
__device__ int     g_deg[NN];
__device__ float   g_dinv[NN];
__device__ __half2 g_half[(size_t)NN * 32];   // g = (x@W)*dinv[row], fp16, 12.8 MB
__device__ int     g_blocksum[NB];
__device__ int     g_blockoff[NB];
__device__ int     g_row_start[NN + 1];
__device__ int     g_cursor[NN];
__device__ int     g_csr_src[NE];

// ---------------------------------------------------------------------------
// 1) degree counting (in-degree by target col). int32 indices.
// ---------------------------------------------------------------------------
__global__ void zero_deg_kernel(int n) {
    int i = blockIdx.x * blockDim.x + threadIdx.x;
    if (i < n) g_deg[i] = 0;
}

__global__ void count_deg_kernel(const int* __restrict__ ei, int n_edges) {
    int e = blockIdx.x * blockDim.x + threadIdx.x;
    if (e < n_edges) {
        int row = ei[e];
        int col = ei[n_edges + e];
        if ((unsigned)row < NN && (unsigned)col < NN)   // must match fill guard
            atomicAdd(&g_deg[col], 1);
    }
}

// ---------------------------------------------------------------------------
// 1b) exclusive scan of degrees -> row_start (3-kernel block scan);
//     dinv fused into scan_final.
// ---------------------------------------------------------------------------
__global__ void block_sum_kernel(int n) {
    __shared__ int s[256];
    int i = blockIdx.x * 256 + threadIdx.x;
    s[threadIdx.x] = (i < n) ? g_deg[i] : 0;
    __syncthreads();
    for (int st = 128; st > 0; st >>= 1) {
        if (threadIdx.x < st) s[threadIdx.x] += s[threadIdx.x + st];
        __syncthreads();
    }
    if (threadIdx.x == 0) g_blocksum[blockIdx.x] = s[0];
}

__global__ void scan_blocksums_kernel(int nb) {   // single block, 512 threads
    __shared__ int s[512];
    int t = threadIdx.x;
    int v0 = (t < nb) ? g_blocksum[t] : 0;
    s[t] = v0;
    __syncthreads();
    for (int off = 1; off < 512; off <<= 1) {
        int v = (t >= off) ? s[t - off] : 0;
        __syncthreads();
        s[t] += v;
        __syncthreads();
    }
    if (t < nb) g_blockoff[t] = s[t] - v0;        // exclusive
}

__global__ void scan_final_kernel(int n) {
    __shared__ int s[256];
    int i = blockIdx.x * 256 + threadIdx.x;
    int v = (i < n) ? g_deg[i] : 0;
    s[threadIdx.x] = v;
    __syncthreads();
    for (int off = 1; off < 256; off <<= 1) {
        int u = (threadIdx.x >= off) ? s[threadIdx.x - off] : 0;
        __syncthreads();
        s[threadIdx.x] += u;
        __syncthreads();
    }
    int excl = s[threadIdx.x] - v + g_blockoff[blockIdx.x];
    if (i < n) {
        g_row_start[i] = excl;
        g_cursor[i]    = excl;
        g_dinv[i]      = rsqrtf((float)(v + 1));   // +1 self loop (fused)
        if (i == n - 1) g_row_start[n] = excl + v;
    }
}

// ---------------------------------------------------------------------------
// 1c) fill CSR: for each edge, place src at cursor[col]++
// ---------------------------------------------------------------------------
__global__ void fill_csr_kernel(const int* __restrict__ ei, int n_edges) {
    int e = blockIdx.x * blockDim.x + threadIdx.x;
    if (e < n_edges) {
        int row = ei[e];
        int col = ei[n_edges + e];
        if ((unsigned)row < NN && (unsigned)col < NN) {
            int pos = atomicAdd(&g_cursor[col], 1);
            g_csr_src[pos] = row;
        }
    }
}

// ---------------------------------------------------------------------------
// 2) h = x @ W via tf32 mma.sync (m16n8k8), g = h * dinv[row] -> g_half (fp16).
// ---------------------------------------------------------------------------
__device__ __forceinline__ unsigned f2tf32(float f) {
    unsigned r;
    asm("cvt.rna.tf32.f32 %0, %1;" : "=r"(r) : "f"(f));
    return r;
}

__device__ __forceinline__ void mma_tf32(float c[4], const unsigned a[4],
                                         const unsigned b[2]) {
    asm volatile(
        "mma.sync.aligned.m16n8k8.row.col.f32.tf32.tf32.f32 "
        "{%0,%1,%2,%3}, {%4,%5,%6,%7}, {%8,%9}, {%0,%1,%2,%3};"
        : "+f"(c[0]), "+f"(c[1]), "+f"(c[2]), "+f"(c[3])
        : "r"(a[0]), "r"(a[1]), "r"(a[2]), "r"(a[3]), "r"(b[0]), "r"(b[1]));
}

#define AS_STRIDE 20
#define BS_STRIDE 68

__global__ __launch_bounds__(256) void gemm_tc_kernel(
    const float* __restrict__ x, const float* __restrict__ W, int n)
{
    __shared__ unsigned As[128 * AS_STRIDE];
    __shared__ unsigned Bs[16 * BS_STRIDE];

    const int tid  = threadIdx.x;
    const int wid  = tid >> 5;
    const int lane = tid & 31;
    const int gid  = lane >> 2;
    const int tig  = lane & 3;
    const int wm   = wid & 3;
    const int wn   = wid >> 2;
    const int m0   = blockIdx.x * 128;

    float c[2][4][4];
#pragma unroll
    for (int s = 0; s < 2; s++)
#pragma unroll
        for (int t = 0; t < 4; t++)
#pragma unroll
            for (int f = 0; f < 4; f++) c[s][t][f] = 0.0f;

    for (int bk = 0; bk < IN_CH / 16; bk++) {
        const int k0 = bk * 16;
#pragma unroll
        for (int i = 0; i < 2; i++) {
            const int f4 = tid + i * 256;
            const int r  = f4 >> 2;
            const int c4 = (f4 & 3) * 4;
            float4 v = make_float4(0.f, 0.f, 0.f, 0.f);
            const int gr = m0 + r;
            if (gr < n)
                v = *(const float4*)(x + (size_t)gr * IN_CH + k0 + c4);
            unsigned* dst = &As[r * AS_STRIDE + c4];
            dst[0] = f2tf32(v.x); dst[1] = f2tf32(v.y);
            dst[2] = f2tf32(v.z); dst[3] = f2tf32(v.w);
        }
        {
            const int r  = tid >> 4;
            const int c4 = (tid & 15) * 4;
            float4 v = *(const float4*)(W + (size_t)(k0 + r) * OUT_CH + c4);
            unsigned* dst = &Bs[r * BS_STRIDE + c4];
            dst[0] = f2tf32(v.x); dst[1] = f2tf32(v.y);
            dst[2] = f2tf32(v.z); dst[3] = f2tf32(v.w);
        }
        __syncthreads();

#pragma unroll
        for (int ks = 0; ks < 2; ks++) {
            const int kb = ks * 8;
            unsigned a[2][4];
#pragma unroll
            for (int s = 0; s < 2; s++) {
                const int rbase = (wm * 32 + s * 16 + gid) * AS_STRIDE;
                a[s][0] = As[rbase + kb + tig];
                a[s][1] = As[rbase + 8 * AS_STRIDE + kb + tig];
                a[s][2] = As[rbase + kb + tig + 4];
                a[s][3] = As[rbase + 8 * AS_STRIDE + kb + tig + 4];
            }
            unsigned b[4][2];
#pragma unroll
            for (int t = 0; t < 4; t++) {
                const int nb = wn * 32 + t * 8 + gid;
                b[t][0] = Bs[(kb + tig) * BS_STRIDE + nb];
                b[t][1] = Bs[(kb + tig + 4) * BS_STRIDE + nb];
            }
#pragma unroll
            for (int s = 0; s < 2; s++)
#pragma unroll
                for (int t = 0; t < 4; t++)
                    mma_tf32(c[s][t], a[s], b[t]);
        }
        __syncthreads();
    }

    // epilogue: scale by dinv[row], convert to fp16, write g_half
#pragma unroll
    for (int s = 0; s < 2; s++) {
#pragma unroll
        for (int h = 0; h < 2; h++) {
            const int row = m0 + wm * 32 + s * 16 + gid + h * 8;
            if (row < n) {
                const float di = g_dinv[row];
#pragma unroll
                for (int t = 0; t < 4; t++) {
                    const int col = wn * 32 + t * 8 + tig * 2;   // even
                    const float vx = c[s][t][h * 2 + 0] * di;
                    const float vy = c[s][t][h * 2 + 1] * di;
                    g_half[(size_t)row * 32 + (col >> 1)] = __floats2half2_rn(vx, vy);
                }
            }
        }
    }
}

// ---------------------------------------------------------------------------
// 3) pull: one warp per node. acc = g[c] + sum_{src in N(c)} g[src] (f32 acc
//    over fp16 gathers); out[c] = acc * dinv[c] + b. No atomics. Each lane
//    owns one __half2 (2 cols) -> warp reads 128 B per source row.
// ---------------------------------------------------------------------------
__global__ __launch_bounds__(256) void pull_kernel(
    float* __restrict__ out, const float* __restrict__ bias, int n)
{
    const int warp = (blockIdx.x * 256 + threadIdx.x) >> 5;
    const int lane = threadIdx.x & 31;
    if (warp >= n) return;

    const int start = g_row_start[warp];
    const int end   = g_row_start[warp + 1];

    float2 acc = __half22float2(g_half[(size_t)warp * 32 + lane]);  // self loop

    for (int j = start; j < end; j += 32) {
        const int id  = (j + lane < end) ? g_csr_src[j + lane] : 0;
        const int cnt = min(32, end - j);
        for (int k = 0; k < cnt; k++) {
            const int src = __shfl_sync(0xffffffff, id, k);
            if ((unsigned)src < NN) {
                float2 v = __half22float2(g_half[(size_t)src * 32 + lane]);
                acc.x += v.x;
                acc.y += v.y;
            }
        }
    }

    const float di = g_dinv[warp];
    float2 bb = ((const float2*)bias)[lane];
    float2 o;
    o.x = acc.x * di + bb.x;
    o.y = acc.y * di + bb.y;
    ((float2*)out)[(size_t)warp * 32 + lane] = o;
}

// ---------------------------------------------------------------------------
extern "C" void kernel_launch(void* const* d_in, const int* in_sizes, int n_in,
                              void* d_out, int out_size)
{
    const float* x  = (const float*)d_in[0];
    const int*   ei = (const int*)d_in[1];     // int32 edge_index [2, E]
    const float* W  = (const float*)d_in[2];
    const float* b  = (const float*)d_in[3];
    float*       out = (float*)d_out;

    const int n = in_sizes[0] / IN_CH;   // 100000
    const int e = in_sizes[1] / 2;       // 1600000

    zero_deg_kernel<<<(n + 255) / 256, 256>>>(n);
    count_deg_kernel<<<(e + 255) / 256, 256>>>(ei, e);

    const int nb = (n + 255) / 256;
    block_sum_kernel<<<nb, 256>>>(n);
    scan_blocksums_kernel<<<1, 512>>>(nb);
    scan_final_kernel<<<nb, 256>>>(n);   // also writes g_dinv + g_cursor

    gemm_tc_kernel<<<(n + 127) / 128, 256>>>(x, W, n);

    fill_csr_kernel<<<(e + 255) / 256, 256>>>(ei, e);

    pull_kernel<<<(n * 32 + 255) / 256, 256>>>(out, b, n);
}

// round 9
// speedup vs baseline: 2.7940x; 1.0731x over previous
#include <cuda_runtime.h>
#include <cuda_fp16.h>
#include <cstdint>

#define NN 100000
#define NE 1600000
#define IN_CH 128
#define OUT_CH 64
#define NB 391            // ceil(NN / 256)

// Scratch (device globals: no allocation allowed in kernel_launch).
__device__ int     g_deg[NN];
__device__ float   g_dinv[NN];
__device__ __half2 g_half[(size_t)NN * 32];   // g = (x@W)*dinv[row], fp16, 12.8 MB
__device__ int     g_blocksum[NB];
__device__ int     g_row_start[NN + 1];
__device__ int     g_cursor[NN];
__device__ int     g_csr_src[NE];

// ---------------------------------------------------------------------------
// 1) degree counting (in-degree by target col). int32 indices.
// ---------------------------------------------------------------------------
__global__ void zero_deg_kernel(int n) {
    int i = blockIdx.x * blockDim.x + threadIdx.x;
    if (i < n) g_deg[i] = 0;
}

__global__ void count_deg_kernel(const int* __restrict__ ei, int n_edges) {
    int e = blockIdx.x * blockDim.x + threadIdx.x;
    if (e < n_edges) {
        int row = ei[e];
        int col = ei[n_edges + e];
        if ((unsigned)row < NN && (unsigned)col < NN)   // must match fill guard
            atomicAdd(&g_deg[col], 1);
    }
}

// ---------------------------------------------------------------------------
// 1b) scan: block sums, then a single final kernel that (a) reduces its own
//     block-offset from g_blocksum, (b) intra-block exclusive scan,
//     (c) writes row_start/cursor and fused dinv.
// ---------------------------------------------------------------------------
__global__ void block_sum_kernel(int n) {
    __shared__ int s[256];
    int i = blockIdx.x * 256 + threadIdx.x;
    s[threadIdx.x] = (i < n) ? g_deg[i] : 0;
    __syncthreads();
    for (int st = 128; st > 0; st >>= 1) {
        if (threadIdx.x < st) s[threadIdx.x] += s[threadIdx.x + st];
        __syncthreads();
    }
    if (threadIdx.x == 0) g_blocksum[blockIdx.x] = s[0];
}

__global__ void scan_final_kernel(int n, int nb) {
    __shared__ int s[256];
    __shared__ int s_off;

    // (a) block offset = sum of blocksums before this block
    int partial = 0;
    for (int t = threadIdx.x; t < blockIdx.x; t += 256)
        partial += g_blocksum[t];
    s[threadIdx.x] = partial;
    __syncthreads();
    for (int st = 128; st > 0; st >>= 1) {
        if (threadIdx.x < st) s[threadIdx.x] += s[threadIdx.x + st];
        __syncthreads();
    }
    if (threadIdx.x == 0) s_off = s[0];
    __syncthreads();
    const int blockoff = s_off;
    __syncthreads();

    // (b) intra-block inclusive scan of degrees
    int i = blockIdx.x * 256 + threadIdx.x;
    int v = (i < n) ? g_deg[i] : 0;
    s[threadIdx.x] = v;
    __syncthreads();
    for (int off = 1; off < 256; off <<= 1) {
        int u = (threadIdx.x >= off) ? s[threadIdx.x - off] : 0;
        __syncthreads();
        s[threadIdx.x] += u;
        __syncthreads();
    }

    // (c) outputs
    int excl = s[threadIdx.x] - v + blockoff;
    if (i < n) {
        g_row_start[i] = excl;
        g_cursor[i]    = excl;
        g_dinv[i]      = rsqrtf((float)(v + 1));   // +1 self loop (fused)
        if (i == n - 1) g_row_start[n] = excl + v;
    }
}

// ---------------------------------------------------------------------------
// 1c) fill CSR: for each edge, place src at cursor[col]++
// ---------------------------------------------------------------------------
__global__ void fill_csr_kernel(const int* __restrict__ ei, int n_edges) {
    int e = blockIdx.x * blockDim.x + threadIdx.x;
    if (e < n_edges) {
        int row = ei[e];
        int col = ei[n_edges + e];
        if ((unsigned)row < NN && (unsigned)col < NN) {
            int pos = atomicAdd(&g_cursor[col], 1);
            g_csr_src[pos] = row;
        }
    }
}

// ---------------------------------------------------------------------------
// 2) h = x @ W via tf32 mma.sync (m16n8k8), g = h * dinv[row] -> g_half (fp16).
// ---------------------------------------------------------------------------
__device__ __forceinline__ unsigned f2tf32(float f) {
    unsigned r;
    asm("cvt.rna.tf32.f32 %0, %1;" : "=r"(r) : "f"(f));
    return r;
}

__device__ __forceinline__ void mma_tf32(float c[4], const unsigned a[4],
                                         const unsigned b[2]) {
    asm volatile(
        "mma.sync.aligned.m16n8k8.row.col.f32.tf32.tf32.f32 "
        "{%0,%1,%2,%3}, {%4,%5,%6,%7}, {%8,%9}, {%0,%1,%2,%3};"
        : "+f"(c[0]), "+f"(c[1]), "+f"(c[2]), "+f"(c[3])
        : "r"(a[0]), "r"(a[1]), "r"(a[2]), "r"(a[3]), "r"(b[0]), "r"(b[1]));
}

#define AS_STRIDE 20
#define BS_STRIDE 68

__global__ __launch_bounds__(256) void gemm_tc_kernel(
    const float* __restrict__ x, const float* __restrict__ W, int n)
{
    __shared__ unsigned As[128 * AS_STRIDE];
    __shared__ unsigned Bs[16 * BS_STRIDE];

    const int tid  = threadIdx.x;
    const int wid  = tid >> 5;
    const int lane = tid & 31;
    const int gid  = lane >> 2;
    const int tig  = lane & 3;
    const int wm   = wid & 3;
    const int wn   = wid >> 2;
    const int m0   = blockIdx.x * 128;

    float c[2][4][4];
#pragma unroll
    for (int s = 0; s < 2; s++)
#pragma unroll
        for (int t = 0; t < 4; t++)
#pragma unroll
            for (int f = 0; f < 4; f++) c[s][t][f] = 0.0f;

    for (int bk = 0; bk < IN_CH / 16; bk++) {
        const int k0 = bk * 16;
#pragma unroll
        for (int i = 0; i < 2; i++) {
            const int f4 = tid + i * 256;
            const int r  = f4 >> 2;
            const int c4 = (f4 & 3) * 4;
            float4 v = make_float4(0.f, 0.f, 0.f, 0.f);
            const int gr = m0 + r;
            if (gr < n)
                v = *(const float4*)(x + (size_t)gr * IN_CH + k0 + c4);
            unsigned* dst = &As[r * AS_STRIDE + c4];
            dst[0] = f2tf32(v.x); dst[1] = f2tf32(v.y);
            dst[2] = f2tf32(v.z); dst[3] = f2tf32(v.w);
        }
        {
            const int r  = tid >> 4;
            const int c4 = (tid & 15) * 4;
            float4 v = *(const float4*)(W + (size_t)(k0 + r) * OUT_CH + c4);
            unsigned* dst = &Bs[r * BS_STRIDE + c4];
            dst[0] = f2tf32(v.x); dst[1] = f2tf32(v.y);
            dst[2] = f2tf32(v.z); dst[3] = f2tf32(v.w);
        }
        __syncthreads();

#pragma unroll
        for (int ks = 0; ks < 2; ks++) {
            const int kb = ks * 8;
            unsigned a[2][4];
#pragma unroll
            for (int s = 0; s < 2; s++) {
                const int rbase = (wm * 32 + s * 16 + gid) * AS_STRIDE;
                a[s][0] = As[rbase + kb + tig];
                a[s][1] = As[rbase + 8 * AS_STRIDE + kb + tig];
                a[s][2] = As[rbase + kb + tig + 4];
                a[s][3] = As[rbase + 8 * AS_STRIDE + kb + tig + 4];
            }
            unsigned b[4][2];
#pragma unroll
            for (int t = 0; t < 4; t++) {
                const int nb = wn * 32 + t * 8 + gid;
                b[t][0] = Bs[(kb + tig) * BS_STRIDE + nb];
                b[t][1] = Bs[(kb + tig + 4) * BS_STRIDE + nb];
            }
#pragma unroll
            for (int s = 0; s < 2; s++)
#pragma unroll
                for (int t = 0; t < 4; t++)
                    mma_tf32(c[s][t], a[s], b[t]);
        }
        __syncthreads();
    }

    // epilogue: scale by dinv[row], convert to fp16, write g_half
#pragma unroll
    for (int s = 0; s < 2; s++) {
#pragma unroll
        for (int h = 0; h < 2; h++) {
            const int row = m0 + wm * 32 + s * 16 + gid + h * 8;
            if (row < n) {
                const float di = g_dinv[row];
#pragma unroll
                for (int t = 0; t < 4; t++) {
                    const int col = wn * 32 + t * 8 + tig * 2;   // even
                    const float vx = c[s][t][h * 2 + 0] * di;
                    const float vy = c[s][t][h * 2 + 1] * di;
                    g_half[(size_t)row * 32 + (col >> 1)] = __floats2half2_rn(vx, vy);
                }
            }
        }
    }
}

// ---------------------------------------------------------------------------
// 3) pull: one warp per node, MLP-4 inner loop. acc = g[c] + sum g[src];
//    out[c] = acc * dinv[c] + b. CSR entries were written only for valid
//    row/col, so no per-gather bounds check needed.
// ---------------------------------------------------------------------------
__global__ __launch_bounds__(256) void pull_kernel(
    float* __restrict__ out, const float* __restrict__ bias, int n)
{
    const int warp = (blockIdx.x * 256 + threadIdx.x) >> 5;
    const int lane = threadIdx.x & 31;
    if (warp >= n) return;

    const int start = g_row_start[warp];
    const int end   = g_row_start[warp + 1];

    float2 acc = __half22float2(g_half[(size_t)warp * 32 + lane]);  // self loop

    for (int j = start; j < end; j += 32) {
        const int id  = (j + lane < end) ? g_csr_src[j + lane] : 0;
        const int cnt = min(32, end - j);
        int k = 0;
        for (; k + 4 <= cnt; k += 4) {
            const int s0 = __shfl_sync(0xffffffff, id, k + 0);
            const int s1 = __shfl_sync(0xffffffff, id, k + 1);
            const int s2 = __shfl_sync(0xffffffff, id, k + 2);
            const int s3 = __shfl_sync(0xffffffff, id, k + 3);
            // 4 independent gathers in flight
            const float2 v0 = __half22float2(g_half[(size_t)s0 * 32 + lane]);
            const float2 v1 = __half22float2(g_half[(size_t)s1 * 32 + lane]);
            const float2 v2 = __half22float2(g_half[(size_t)s2 * 32 + lane]);
            const float2 v3 = __half22float2(g_half[(size_t)s3 * 32 + lane]);
            acc.x += (v0.x + v1.x) + (v2.x + v3.x);
            acc.y += (v0.y + v1.y) + (v2.y + v3.y);
        }
        for (; k < cnt; k++) {
            const int src = __shfl_sync(0xffffffff, id, k);
            const float2 v = __half22float2(g_half[(size_t)src * 32 + lane]);
            acc.x += v.x;
            acc.y += v.y;
        }
    }

    const float di = g_dinv[warp];
    float2 bb = ((const float2*)bias)[lane];
    float2 o;
    o.x = acc.x * di + bb.x;
    o.y = acc.y * di + bb.y;
    ((float2*)out)[(size_t)warp * 32 + lane] = o;
}

// ---------------------------------------------------------------------------
extern "C" void kernel_launch(void* const* d_in, const int* in_sizes, int n_in,
                              void* d_out, int out_size)
{
    const float* x  = (const float*)d_in[0];
    const int*   ei = (const int*)d_in[1];     // int32 edge_index [2, E]
    const float* W  = (const float*)d_in[2];
    const float* b  = (const float*)d_in[3];
    float*       out = (float*)d_out;

    const int n = in_sizes[0] / IN_CH;   // 100000
    const int e = in_sizes[1] / 2;       // 1600000

    zero_deg_kernel<<<(n + 255) / 256, 256>>>(n);
    count_deg_kernel<<<(e + 255) / 256, 256>>>(ei, e);

    const int nb = (n + 255) / 256;
    block_sum_kernel<<<nb, 256>>>(n);
    scan_final_kernel<<<nb, 256>>>(n, nb);   // block-offset + scan + dinv fused

    gemm_tc_kernel<<<(n + 127) / 128, 256>>>(x, W, n);

    fill_csr_kernel<<<(e + 255) / 256, 256>>>(ei, e);

    pull_kernel<<<(n * 32 + 255) / 256, 256>>>(out, b, n);
}

// round 10
// speedup vs baseline: 2.8620x; 1.0244x over previous
#include <cuda_runtime.h>
#include <cuda_fp16.h>
#include <cstdint>

#define NN 100000
#define NE 1600000
#define IN_CH 128
#define OUT_CH 64
#define NKSTEPS (IN_CH / 16)   // 8

// Scratch (device globals: no allocation allowed in kernel_launch).
__device__ int     g_deg[NN];
__device__ float   g_dinv[NN];
__device__ __half2 g_half[(size_t)NN * 32];   // g = (x@W)*dinv[row], fp16, 12.8 MB
__device__ int     g_blocksum[512];           // >= NB
__device__ int     g_row_start[NN + 1];
__device__ int     g_cursor[NN];
__device__ int     g_csr_src[NE];

// ---------------------------------------------------------------------------
// 1) degree counting (in-degree by target col). int32 indices.
//    (g_deg zeroed by cudaMemsetAsync host-side.)
// ---------------------------------------------------------------------------
__global__ void count_deg_kernel(const int* __restrict__ ei, int n_edges) {
    int e = blockIdx.x * blockDim.x + threadIdx.x;
    if (e < n_edges) {
        int row = ei[e];
        int col = ei[n_edges + e];
        if ((unsigned)row < NN && (unsigned)col < NN)   // must match fill guard
            atomicAdd(&g_deg[col], 1);
    }
}

// ---------------------------------------------------------------------------
// 1b) scan: block sums, then a final kernel that derives its own block offset,
//     does the intra-block scan, and writes row_start/cursor + fused dinv.
// ---------------------------------------------------------------------------
__global__ void block_sum_kernel(int n) {
    __shared__ int s[256];
    int i = blockIdx.x * 256 + threadIdx.x;
    s[threadIdx.x] = (i < n) ? g_deg[i] : 0;
    __syncthreads();
    for (int st = 128; st > 0; st >>= 1) {
        if (threadIdx.x < st) s[threadIdx.x] += s[threadIdx.x + st];
        __syncthreads();
    }
    if (threadIdx.x == 0) g_blocksum[blockIdx.x] = s[0];
}

__global__ void scan_final_kernel(int n, int nb) {
    __shared__ int s[256];
    __shared__ int s_off;

    int partial = 0;
    for (int t = threadIdx.x; t < blockIdx.x; t += 256)
        partial += g_blocksum[t];
    s[threadIdx.x] = partial;
    __syncthreads();
    for (int st = 128; st > 0; st >>= 1) {
        if (threadIdx.x < st) s[threadIdx.x] += s[threadIdx.x + st];
        __syncthreads();
    }
    if (threadIdx.x == 0) s_off = s[0];
    __syncthreads();
    const int blockoff = s_off;
    __syncthreads();

    int i = blockIdx.x * 256 + threadIdx.x;
    int v = (i < n) ? g_deg[i] : 0;
    s[threadIdx.x] = v;
    __syncthreads();
    for (int off = 1; off < 256; off <<= 1) {
        int u = (threadIdx.x >= off) ? s[threadIdx.x - off] : 0;
        __syncthreads();
        s[threadIdx.x] += u;
        __syncthreads();
    }

    int excl = s[threadIdx.x] - v + blockoff;
    if (i < n) {
        g_row_start[i] = excl;
        g_cursor[i]    = excl;
        g_dinv[i]      = rsqrtf((float)(v + 1));   // +1 self loop (fused)
        if (i == n - 1) g_row_start[n] = excl + v;
    }
}

// ---------------------------------------------------------------------------
// 1c) fill CSR: for each edge, place src at cursor[col]++
// ---------------------------------------------------------------------------
__global__ void fill_csr_kernel(const int* __restrict__ ei, int n_edges) {
    int e = blockIdx.x * blockDim.x + threadIdx.x;
    if (e < n_edges) {
        int row = ei[e];
        int col = ei[n_edges + e];
        if ((unsigned)row < NN && (unsigned)col < NN) {
            int pos = atomicAdd(&g_cursor[col], 1);
            g_csr_src[pos] = row;
        }
    }
}

// ---------------------------------------------------------------------------
// 2) h = x @ W via tf32 mma.sync, cp.async double-buffered pipeline.
//    g = h * dinv[row] -> g_half (fp16).
// ---------------------------------------------------------------------------
__device__ __forceinline__ unsigned f2tf32(float f) {
    unsigned r;
    asm("cvt.rna.tf32.f32 %0, %1;" : "=r"(r) : "f"(f));
    return r;
}

__device__ __forceinline__ void mma_tf32(float c[4], const unsigned a[4],
                                         const unsigned b[2]) {
    asm volatile(
        "mma.sync.aligned.m16n8k8.row.col.f32.tf32.tf32.f32 "
        "{%0,%1,%2,%3}, {%4,%5,%6,%7}, {%8,%9}, {%0,%1,%2,%3};"
        : "+f"(c[0]), "+f"(c[1]), "+f"(c[2]), "+f"(c[3])
        : "r"(a[0]), "r"(a[1]), "r"(a[2]), "r"(a[3]), "r"(b[0]), "r"(b[1]));
}

__device__ __forceinline__ void cp16(void* smem_dst, const void* gmem_src, bool pred) {
    unsigned saddr = (unsigned)__cvta_generic_to_shared(smem_dst);
    int sz = pred ? 16 : 0;
    asm volatile("cp.async.cg.shared.global [%0], [%1], 16, %2;"
                 :: "r"(saddr), "l"(gmem_src), "r"(sz));
}
#define CP_COMMIT()  asm volatile("cp.async.commit_group;")
#define CP_WAIT(N)   asm volatile("cp.async.wait_group %0;" :: "n"(N))

#define AS_STRIDE 20   // (r*20 + c4)*4 bytes: 80*r + 16*c — 16B aligned chunks
#define BS_STRIDE 68   // 272*r + 16*c — 16B aligned

__global__ __launch_bounds__(256) void gemm_tc_kernel(
    const float* __restrict__ x, const float* __restrict__ W, int n)
{
    __shared__ unsigned As[2][128 * AS_STRIDE];  // raw f32 bits
    __shared__ unsigned Bs[2][16 * BS_STRIDE];

    const int tid  = threadIdx.x;
    const int wid  = tid >> 5;
    const int lane = tid & 31;
    const int gid  = lane >> 2;
    const int tig  = lane & 3;
    const int wm   = wid & 3;
    const int wn   = wid >> 2;
    const int m0   = blockIdx.x * 128;

    // loader indices (fixed per thread)
    const int r0  = tid >> 2;            // x row for i=0 (0..63)
    const int r1  = r0 + 64;             // x row for i=1
    const int c4x = (tid & 3) * 4;       // x k-offset
    const int rW  = tid >> 4;            // W row 0..15
    const int c4W = (tid & 15) * 4;      // W col offset

    auto load_stage = [&](int st, int bk) {
        const int k0 = bk * 16;
        // x rows (zfill out-of-range)
        {
            const int gr = m0 + r0;
            const bool p = gr < n;
            const float* src = x + (size_t)(p ? gr : 0) * IN_CH + k0 + c4x;
            cp16(&As[st][r0 * AS_STRIDE + c4x], src, p);
        }
        {
            const int gr = m0 + r1;
            const bool p = gr < n;
            const float* src = x + (size_t)(p ? gr : 0) * IN_CH + k0 + c4x;
            cp16(&As[st][r1 * AS_STRIDE + c4x], src, p);
        }
        // W
        cp16(&Bs[st][rW * BS_STRIDE + c4W], W + (size_t)(k0 + rW) * OUT_CH + c4W, true);
        CP_COMMIT();
    };

    float c[2][4][4];
#pragma unroll
    for (int s = 0; s < 2; s++)
#pragma unroll
        for (int t = 0; t < 4; t++)
#pragma unroll
            for (int f = 0; f < 4; f++) c[s][t][f] = 0.0f;

    load_stage(0, 0);

    for (int bk = 0; bk < NKSTEPS; bk++) {
        const int cur = bk & 1;
        if (bk + 1 < NKSTEPS) {
            load_stage(cur ^ 1, bk + 1);
            CP_WAIT(1);                 // current stage complete
        } else {
            CP_WAIT(0);
        }
        __syncthreads();

#pragma unroll
        for (int ks = 0; ks < 2; ks++) {
            const int kb = ks * 8;
            unsigned a[2][4];
#pragma unroll
            for (int s = 0; s < 2; s++) {
                const int rbase = (wm * 32 + s * 16 + gid) * AS_STRIDE;
                a[s][0] = f2tf32(__uint_as_float(As[cur][rbase + kb + tig]));
                a[s][1] = f2tf32(__uint_as_float(As[cur][rbase + 8 * AS_STRIDE + kb + tig]));
                a[s][2] = f2tf32(__uint_as_float(As[cur][rbase + kb + tig + 4]));
                a[s][3] = f2tf32(__uint_as_float(As[cur][rbase + 8 * AS_STRIDE + kb + tig + 4]));
            }
            unsigned b[4][2];
#pragma unroll
            for (int t = 0; t < 4; t++) {
                const int nb = wn * 32 + t * 8 + gid;
                b[t][0] = f2tf32(__uint_as_float(Bs[cur][(kb + tig) * BS_STRIDE + nb]));
                b[t][1] = f2tf32(__uint_as_float(Bs[cur][(kb + tig + 4) * BS_STRIDE + nb]));
            }
#pragma unroll
            for (int s = 0; s < 2; s++)
#pragma unroll
                for (int t = 0; t < 4; t++)
                    mma_tf32(c[s][t], a[s], b[t]);
        }
        __syncthreads();   // protect stage buffer before it is reloaded
    }

    // epilogue: scale by dinv[row], convert to fp16, write g_half
#pragma unroll
    for (int s = 0; s < 2; s++) {
#pragma unroll
        for (int h = 0; h < 2; h++) {
            const int row = m0 + wm * 32 + s * 16 + gid + h * 8;
            if (row < n) {
                const float di = g_dinv[row];
#pragma unroll
                for (int t = 0; t < 4; t++) {
                    const int col = wn * 32 + t * 8 + tig * 2;
                    const float vx = c[s][t][h * 2 + 0] * di;
                    const float vy = c[s][t][h * 2 + 1] * di;
                    g_half[(size_t)row * 32 + (col >> 1)] = __floats2half2_rn(vx, vy);
                }
            }
        }
    }
}

// ---------------------------------------------------------------------------
// 3) pull: one warp per node, MLP-8 inner loop. acc = g[c] + sum g[src];
//    out[c] = acc * dinv[c] + b.
// ---------------------------------------------------------------------------
__global__ __launch_bounds__(256) void pull_kernel(
    float* __restrict__ out, const float* __restrict__ bias, int n)
{
    const int warp = (blockIdx.x * 256 + threadIdx.x) >> 5;
    const int lane = threadIdx.x & 31;
    if (warp >= n) return;

    const int start = g_row_start[warp];
    const int end   = g_row_start[warp + 1];

    float2 acc = __half22float2(g_half[(size_t)warp * 32 + lane]);  // self loop

    for (int j = start; j < end; j += 32) {
        const int id  = (j + lane < end) ? g_csr_src[j + lane] : 0;
        const int cnt = min(32, end - j);
        int k = 0;
        for (; k + 8 <= cnt; k += 8) {
            int s[8];
#pragma unroll
            for (int u = 0; u < 8; u++)
                s[u] = __shfl_sync(0xffffffff, id, k + u);
            float2 v[8];
#pragma unroll
            for (int u = 0; u < 8; u++)
                v[u] = __half22float2(g_half[(size_t)s[u] * 32 + lane]);
            acc.x += ((v[0].x + v[1].x) + (v[2].x + v[3].x))
                   + ((v[4].x + v[5].x) + (v[6].x + v[7].x));
            acc.y += ((v[0].y + v[1].y) + (v[2].y + v[3].y))
                   + ((v[4].y + v[5].y) + (v[6].y + v[7].y));
        }
        for (; k + 4 <= cnt; k += 4) {
            int s0 = __shfl_sync(0xffffffff, id, k + 0);
            int s1 = __shfl_sync(0xffffffff, id, k + 1);
            int s2 = __shfl_sync(0xffffffff, id, k + 2);
            int s3 = __shfl_sync(0xffffffff, id, k + 3);
            float2 v0 = __half22float2(g_half[(size_t)s0 * 32 + lane]);
            float2 v1 = __half22float2(g_half[(size_t)s1 * 32 + lane]);
            float2 v2 = __half22float2(g_half[(size_t)s2 * 32 + lane]);
            float2 v3 = __half22float2(g_half[(size_t)s3 * 32 + lane]);
            acc.x += (v0.x + v1.x) + (v2.x + v3.x);
            acc.y += (v0.y + v1.y) + (v2.y + v3.y);
        }
        for (; k < cnt; k++) {
            const int src = __shfl_sync(0xffffffff, id, k);
            const float2 v = __half22float2(g_half[(size_t)src * 32 + lane]);
            acc.x += v.x;
            acc.y += v.y;
        }
    }

    const float di = g_dinv[warp];
    float2 bb = ((const float2*)bias)[lane];
    float2 o;
    o.x = acc.x * di + bb.x;
    o.y = acc.y * di + bb.y;
    ((float2*)out)[(size_t)warp * 32 + lane] = o;
}

// ---------------------------------------------------------------------------
extern "C" void kernel_launch(void* const* d_in, const int* in_sizes, int n_in,
                              void* d_out, int out_size)
{
    const float* x  = (const float*)d_in[0];
    const int*   ei = (const int*)d_in[1];     // int32 edge_index [2, E]
    const float* W  = (const float*)d_in[2];
    const float* b  = (const float*)d_in[3];
    float*       out = (float*)d_out;

    const int n = in_sizes[0] / IN_CH;   // 100000
    const int e = in_sizes[1] / 2;       // 1600000

    // zero degrees via async memset (graph-capturable, no allocation)
    void* deg_ptr = nullptr;
    cudaGetSymbolAddress(&deg_ptr, g_deg);
    cudaMemsetAsync(deg_ptr, 0, (size_t)n * sizeof(int));

    count_deg_kernel<<<(e + 255) / 256, 256>>>(ei, e);

    const int nb = (n + 255) / 256;
    block_sum_kernel<<<nb, 256>>>(n);
    scan_final_kernel<<<nb, 256>>>(n, nb);   // block-offset + scan + dinv fused

    gemm_tc_kernel<<<(n + 127) / 128, 256>>>(x, W, n);

    fill_csr_kernel<<<(e + 255) / 256, 256>>>(ei, e);

    pull_kernel<<<(n * 32 + 255) / 256, 256>>>(out, b, n);
}

// round 11
// speedup vs baseline: 2.9695x; 1.0376x over previous
#include <cuda_runtime.h>
#include <cuda_fp16.h>
#include <cstdint>

#define NN 100000
#define NE 1600000
#define IN_CH 128
#define OUT_CH 64
#define NKSTEPS (IN_CH / 16)   // 8

// Scratch (device globals: no allocation allowed in kernel_launch).
__device__ int     g_deg[NN];
__device__ float   g_dinv[NN];
__device__ __half2 g_half[(size_t)NN * 32];   // g = (x@W)*dinv[row], fp16, 12.8 MB
__device__ int     g_blocksum[512];           // >= NB
__device__ int     g_row_start[NN + 1];
__device__ int     g_cursor[NN];
__device__ int     g_csr_src[NE];

// ---------------------------------------------------------------------------
// 1) degree counting (in-degree by target col). int32 indices.
//    (g_deg zeroed by cudaMemsetAsync host-side.)
// ---------------------------------------------------------------------------
__global__ void count_deg_kernel(const int* __restrict__ ei, int n_edges) {
    int e = blockIdx.x * blockDim.x + threadIdx.x;
    if (e < n_edges) {
        int row = ei[e];
        int col = ei[n_edges + e];
        if ((unsigned)row < NN && (unsigned)col < NN)   // must match fill guard
            atomicAdd(&g_deg[col], 1);
    }
}

// ---------------------------------------------------------------------------
// 1b) scan: block sums, then a final kernel that derives its own block offset,
//     does the intra-block scan, and writes row_start/cursor + fused dinv.
// ---------------------------------------------------------------------------
__global__ void block_sum_kernel(int n) {
    __shared__ int s[256];
    int i = blockIdx.x * 256 + threadIdx.x;
    s[threadIdx.x] = (i < n) ? g_deg[i] : 0;
    __syncthreads();
    for (int st = 128; st > 0; st >>= 1) {
        if (threadIdx.x < st) s[threadIdx.x] += s[threadIdx.x + st];
        __syncthreads();
    }
    if (threadIdx.x == 0) g_blocksum[blockIdx.x] = s[0];
}

__global__ void scan_final_kernel(int n, int nb) {
    __shared__ int s[256];
    __shared__ int s_off;

    int partial = 0;
    for (int t = threadIdx.x; t < blockIdx.x; t += 256)
        partial += g_blocksum[t];
    s[threadIdx.x] = partial;
    __syncthreads();
    for (int st = 128; st > 0; st >>= 1) {
        if (threadIdx.x < st) s[threadIdx.x] += s[threadIdx.x + st];
        __syncthreads();
    }
    if (threadIdx.x == 0) s_off = s[0];
    __syncthreads();
    const int blockoff = s_off;
    __syncthreads();

    int i = blockIdx.x * 256 + threadIdx.x;
    int v = (i < n) ? g_deg[i] : 0;
    s[threadIdx.x] = v;
    __syncthreads();
    for (int off = 1; off < 256; off <<= 1) {
        int u = (threadIdx.x >= off) ? s[threadIdx.x - off] : 0;
        __syncthreads();
        s[threadIdx.x] += u;
        __syncthreads();
    }

    int excl = s[threadIdx.x] - v + blockoff;
    if (i < n) {
        g_row_start[i] = excl;
        g_cursor[i]    = excl;
        g_dinv[i]      = rsqrtf((float)(v + 1));   // +1 self loop (fused)
        if (i == n - 1) g_row_start[n] = excl + v;
    }
}

// ---------------------------------------------------------------------------
// 1c) fill CSR: for each edge, place src at cursor[col]++
// ---------------------------------------------------------------------------
__global__ void fill_csr_kernel(const int* __restrict__ ei, int n_edges) {
    int e = blockIdx.x * blockDim.x + threadIdx.x;
    if (e < n_edges) {
        int row = ei[e];
        int col = ei[n_edges + e];
        if ((unsigned)row < NN && (unsigned)col < NN) {
            int pos = atomicAdd(&g_cursor[col], 1);
            g_csr_src[pos] = row;
        }
    }
}

// ---------------------------------------------------------------------------
// 2) h = x @ W via tf32 mma.sync, 3-stage cp.async pipeline.
//    g = h * dinv[row] -> g_half (fp16).
// ---------------------------------------------------------------------------
__device__ __forceinline__ unsigned f2tf32(float f) {
    unsigned r;
    asm("cvt.rna.tf32.f32 %0, %1;" : "=r"(r) : "f"(f));
    return r;
}

__device__ __forceinline__ void mma_tf32(float c[4], const unsigned a[4],
                                         const unsigned b[2]) {
    asm volatile(
        "mma.sync.aligned.m16n8k8.row.col.f32.tf32.tf32.f32 "
        "{%0,%1,%2,%3}, {%4,%5,%6,%7}, {%8,%9}, {%0,%1,%2,%3};"
        : "+f"(c[0]), "+f"(c[1]), "+f"(c[2]), "+f"(c[3])
        : "r"(a[0]), "r"(a[1]), "r"(a[2]), "r"(a[3]), "r"(b[0]), "r"(b[1]));
}

__device__ __forceinline__ void cp16(void* smem_dst, const void* gmem_src, bool pred) {
    unsigned saddr = (unsigned)__cvta_generic_to_shared(smem_dst);
    int sz = pred ? 16 : 0;
    asm volatile("cp.async.cg.shared.global [%0], [%1], 16, %2;"
                 :: "r"(saddr), "l"(gmem_src), "r"(sz));
}
#define CP_COMMIT()  asm volatile("cp.async.commit_group;")
#define CP_WAIT(N)   asm volatile("cp.async.wait_group %0;" :: "n"(N))

#define AS_STRIDE 20
#define BS_STRIDE 68

__global__ __launch_bounds__(256) void gemm_tc_kernel(
    const float* __restrict__ x, const float* __restrict__ W, int n)
{
    __shared__ unsigned As[3][128 * AS_STRIDE];  // raw f32 bits
    __shared__ unsigned Bs[3][16 * BS_STRIDE];

    const int tid  = threadIdx.x;
    const int wid  = tid >> 5;
    const int lane = tid & 31;
    const int gid  = lane >> 2;
    const int tig  = lane & 3;
    const int wm   = wid & 3;
    const int wn   = wid >> 2;
    const int m0   = blockIdx.x * 128;

    const int r0  = tid >> 2;            // x row for i=0 (0..63)
    const int r1  = r0 + 64;             // x row for i=1
    const int c4x = (tid & 3) * 4;       // x k-offset
    const int rW  = tid >> 4;            // W row 0..15
    const int c4W = (tid & 15) * 4;      // W col offset

    auto load_stage = [&](int st, int bk) {
        const int k0 = bk * 16;
        {
            const int gr = m0 + r0;
            const bool p = gr < n;
            const float* src = x + (size_t)(p ? gr : 0) * IN_CH + k0 + c4x;
            cp16(&As[st][r0 * AS_STRIDE + c4x], src, p);
        }
        {
            const int gr = m0 + r1;
            const bool p = gr < n;
            const float* src = x + (size_t)(p ? gr : 0) * IN_CH + k0 + c4x;
            cp16(&As[st][r1 * AS_STRIDE + c4x], src, p);
        }
        cp16(&Bs[st][rW * BS_STRIDE + c4W], W + (size_t)(k0 + rW) * OUT_CH + c4W, true);
        CP_COMMIT();
    };

    float c[2][4][4];
#pragma unroll
    for (int s = 0; s < 2; s++)
#pragma unroll
        for (int t = 0; t < 4; t++)
#pragma unroll
            for (int f = 0; f < 4; f++) c[s][t][f] = 0.0f;

    load_stage(0, 0);
    load_stage(1, 1);

    for (int bk = 0; bk < NKSTEPS; bk++) {
        const int cur = bk % 3;
        if (bk + 2 < NKSTEPS) {
            load_stage((bk + 2) % 3, bk + 2);
            CP_WAIT(2);                 // groups up to bk complete
        } else if (bk + 1 < NKSTEPS) {
            CP_WAIT(1);
        } else {
            CP_WAIT(0);
        }
        __syncthreads();

#pragma unroll
        for (int ks = 0; ks < 2; ks++) {
            const int kb = ks * 8;
            unsigned a[2][4];
#pragma unroll
            for (int s = 0; s < 2; s++) {
                const int rbase = (wm * 32 + s * 16 + gid) * AS_STRIDE;
                a[s][0] = f2tf32(__uint_as_float(As[cur][rbase + kb + tig]));
                a[s][1] = f2tf32(__uint_as_float(As[cur][rbase + 8 * AS_STRIDE + kb + tig]));
                a[s][2] = f2tf32(__uint_as_float(As[cur][rbase + kb + tig + 4]));
                a[s][3] = f2tf32(__uint_as_float(As[cur][rbase + 8 * AS_STRIDE + kb + tig + 4]));
            }
            unsigned b[4][2];
#pragma unroll
            for (int t = 0; t < 4; t++) {
                const int nb = wn * 32 + t * 8 + gid;
                b[t][0] = f2tf32(__uint_as_float(Bs[cur][(kb + tig) * BS_STRIDE + nb]));
                b[t][1] = f2tf32(__uint_as_float(Bs[cur][(kb + tig + 4) * BS_STRIDE + nb]));
            }
#pragma unroll
            for (int s = 0; s < 2; s++)
#pragma unroll
                for (int t = 0; t < 4; t++)
                    mma_tf32(c[s][t], a[s], b[t]);
        }
        __syncthreads();   // protect stage buffer before it is reloaded
    }

    // epilogue: scale by dinv[row], convert to fp16, write g_half
#pragma unroll
    for (int s = 0; s < 2; s++) {
#pragma unroll
        for (int h = 0; h < 2; h++) {
            const int row = m0 + wm * 32 + s * 16 + gid + h * 8;
            if (row < n) {
                const float di = g_dinv[row];
#pragma unroll
                for (int t = 0; t < 4; t++) {
                    const int col = wn * 32 + t * 8 + tig * 2;
                    const float vx = c[s][t][h * 2 + 0] * di;
                    const float vy = c[s][t][h * 2 + 1] * di;
                    g_half[(size_t)row * 32 + (col >> 1)] = __floats2half2_rn(vx, vy);
                }
            }
        }
    }
}

// ---------------------------------------------------------------------------
// 3) pull v2: one warp per node, HALF-WARP per source row.
//    Each half (16 lanes) gathers a different source row per step; each lane
//    loads uint2 (8 B = 4 cols). float4 accumulator per lane per half,
//    combined with one shfl_xor(16) at the end; lanes 0-15 write the node row.
// ---------------------------------------------------------------------------
__global__ __launch_bounds__(256) void pull_kernel(
    float* __restrict__ out, const float* __restrict__ bias, int n)
{
    const int warp = (blockIdx.x * 256 + threadIdx.x) >> 5;
    const int lane = threadIdx.x & 31;
    if (warp >= n) return;
    const int half = lane >> 4;       // 0 or 1
    const int hl   = lane & 15;       // lane in half

    const int start = g_row_start[warp];
    const int end   = g_row_start[warp + 1];

    const uint2* rows = (const uint2*)g_half;   // 16 uint2 (128 B) per row

    float4 acc = make_float4(0.f, 0.f, 0.f, 0.f);

    // self loop g[c] — half 0 only (avoid double count)
    if (half == 0) {
        uint2 raw = rows[(size_t)warp * 16 + hl];
        float2 a = __half22float2(*(__half2*)&raw.x);
        float2 b = __half22float2(*(__half2*)&raw.y);
        acc.x = a.x; acc.y = a.y; acc.z = b.x; acc.w = b.y;
    }

    for (int j = start; j < end; j += 32) {
        const int id  = (j + lane < end) ? g_csr_src[j + lane] : 0;
        const int cnt = min(32, end - j);
        for (int k = 0; k < cnt; k += 8) {
            uint2 raw[4];
#pragma unroll
            for (int u = 0; u < 4; u++) {
                const int idx = k + u * 2 + half;           // this half's edge
                const int src = __shfl_sync(0xffffffff, id, idx & 31);
                raw[u] = (idx < cnt) ? rows[(size_t)src * 16 + hl]
                                     : make_uint2(0u, 0u);  // +0.0 contribution
            }
#pragma unroll
            for (int u = 0; u < 4; u++) {
                float2 a = __half22float2(*(__half2*)&raw[u].x);
                float2 b = __half22float2(*(__half2*)&raw[u].y);
                acc.x += a.x; acc.y += a.y; acc.z += b.x; acc.w += b.y;
            }
        }
    }

    // combine the two halves
    acc.x += __shfl_xor_sync(0xffffffff, acc.x, 16);
    acc.y += __shfl_xor_sync(0xffffffff, acc.y, 16);
    acc.z += __shfl_xor_sync(0xffffffff, acc.z, 16);
    acc.w += __shfl_xor_sync(0xffffffff, acc.w, 16);

    if (half == 0) {
        const float di = g_dinv[warp];
        const float4 bb = ((const float4*)bias)[hl];
        float4 o;
        o.x = acc.x * di + bb.x;
        o.y = acc.y * di + bb.y;
        o.z = acc.z * di + bb.z;
        o.w = acc.w * di + bb.w;
        ((float4*)out)[(size_t)warp * 16 + hl] = o;
    }
}

// ---------------------------------------------------------------------------
extern "C" void kernel_launch(void* const* d_in, const int* in_sizes, int n_in,
                              void* d_out, int out_size)
{
    const float* x  = (const float*)d_in[0];
    const int*   ei = (const int*)d_in[1];     // int32 edge_index [2, E]
    const float* W  = (const float*)d_in[2];
    const float* b  = (const float*)d_in[3];
    float*       out = (float*)d_out;

    const int n = in_sizes[0] / IN_CH;   // 100000
    const int e = in_sizes[1] / 2;       // 1600000

    void* deg_ptr = nullptr;
    cudaGetSymbolAddress(&deg_ptr, g_deg);
    cudaMemsetAsync(deg_ptr, 0, (size_t)n * sizeof(int));

    count_deg_kernel<<<(e + 255) / 256, 256>>>(ei, e);

    const int nb = (n + 255) / 256;
    block_sum_kernel<<<nb, 256>>>(n);
    scan_final_kernel<<<nb, 256>>>(n, nb);

    gemm_tc_kernel<<<(n + 127) / 128, 256>>>(x, W, n);

    fill_csr_kernel<<<(e + 255) / 256, 256>>>(ei, e);

    pull_kernel<<<(n * 32 + 255) / 256, 256>>>(out, b, n);
}